// round 6
// baseline (speedup 1.0000x reference)
#include <cuda_runtime.h>
#include <math.h>
#include <stdint.h>

// LSTM B=256,T=512,D=256,H=1024,C=128.
// Persistent kernel on mma.sync.m16n8k32.s8 (14-bit fixed-point hi/lo split),
// s32 accum, W tile RESIDENT in smem. 128 CTAs = 2 Mtiles(128) x 64 Ntiles(64).
// Grid barrier per timestep, h double-buffered in int8 hi/lo.

#define BB   256
#define TT   512
#define DD   256
#define HH   1024
#define CCC  128
#define KTOT 1280
#define NTOT 4096
#define GRID 128
#define NTH  256
#define KBLK 128
#define NKB  10
#define QLVL 16256.0f

// smem layout (dynamic):
//   [0,81920)        W_hi resident  (640 rows r=kb*64+nl, 128B each, SW128)
//   [81920,163840)   W_lo resident
//   [163840,229376)  2 A stages x {A_hi 16K, A_lo 16K}
//   [229376,230144)  tables: scx[64], sch[64], bias[64]
#define OFF_WH   0
#define OFF_WL   81920
#define OFF_AST  163840
#define STG_STRIDE 32768
#define OFF_AH   0
#define OFF_AL   16384
#define OFF_TBL  229376
#define SMEM_TOTAL 230144

#define SW(o) ((o) ^ (((o) >> 3) & 0x70))

// ---------------- device globals ----------------
__device__ int8_t  g_W8h[(size_t)NTOT * KTOT];
__device__ int8_t  g_W8l[(size_t)NTOT * KTOT];
__device__ int8_t  g_x8h[(size_t)TT * BB * DD];
__device__ int8_t  g_x8l[(size_t)TT * BB * DD];
__device__ int8_t  g_h8h[2][BB * HH];
__device__ int8_t  g_h8l[2][BB * HH];
__device__ float   g_hf[BB * HH];
__device__ float   g_wmx[NTOT];
__device__ float   g_wmh[NTOT];
__device__ float   g_scx[NTOT];
__device__ float   g_sch[NTOT];
__device__ float   g_bias[NTOT];
__device__ unsigned g_xmax_bits;
__device__ unsigned g_bar;

// ---------------- PTX helpers ----------------
__device__ __forceinline__ uint32_t smem_to_u32(const void* p) {
    uint32_t a;
    asm("{ .reg .u64 t; cvta.to.shared.u64 t, %1; cvt.u32.u64 %0, t; }" : "=r"(a) : "l"(p));
    return a;
}

#define CP16(dst, src) \
    asm volatile("cp.async.cg.shared.global [%0], [%1], 16;" :: "r"(dst), "l"(src) : "memory")
#define CP_COMMIT() asm volatile("cp.async.commit_group;" ::: "memory")
#define CP_WAIT0()  asm volatile("cp.async.wait_group 0;" ::: "memory")
#define CP_WAIT1()  asm volatile("cp.async.wait_group 1;" ::: "memory")

#define LDSM_X4(r0, r1, r2, r3, addr) \
    asm volatile("ldmatrix.sync.aligned.m8n8.x4.shared.b16 {%0,%1,%2,%3}, [%4];" \
                 : "=r"(r0), "=r"(r1), "=r"(r2), "=r"(r3) : "r"(addr))

#define MMA_S8(c, a, b) \
    asm volatile("mma.sync.aligned.m16n8k32.row.col.s32.s8.s8.s32 " \
                 "{%0,%1,%2,%3},{%4,%5,%6,%7},{%8,%9},{%0,%1,%2,%3};" \
                 : "+r"((c)[0]), "+r"((c)[1]), "+r"((c)[2]), "+r"((c)[3]) \
                 : "r"((a)[0]), "r"((a)[1]), "r"((a)[2]), "r"((a)[3]), \
                   "r"((b)[0]), "r"((b)[1]))

// column interleave: within 32-col warp tile, col(u,g)=16*(u>>2)+8*(g>>1)+2*(u&3)+(g&1)
__device__ __forceinline__ void decode_col(int n, int& j, int& g) {
    int o = n & 31, w32 = n >> 5;
    int u = ((o >> 4) << 2) + ((o >> 1) & 3);
    g = ((o >> 3) & 1) * 2 + (o & 1);
    j = w32 * 8 + u;
}

// rounded 128-split: q in [-16256,16256] -> hi in [-127,127], lo in [-64,63]
__device__ __forceinline__ void split_q(int q, int& hi, int& lo) {
    hi = (q + 64) >> 7;
    lo = q - (hi << 7);
}

// ---------------- init kernels ----------------
__global__ void init0_kernel() {
    g_xmax_bits = 0u;
    g_bar = 0u;
}

__global__ void xmax_kernel(const float* __restrict__ x) {
    __shared__ float red[256];
    const long total = (long)TT * BB * DD;
    float m = 0.0f;
    for (long i = (long)blockIdx.x * blockDim.x + threadIdx.x; i < total;
         i += (long)gridDim.x * blockDim.x)
        m = fmaxf(m, fabsf(x[i]));
    red[threadIdx.x] = m;
    __syncthreads();
    for (int s = 128; s > 0; s >>= 1) {
        if (threadIdx.x < s) red[threadIdx.x] = fmaxf(red[threadIdx.x], red[threadIdx.x + s]);
        __syncthreads();
    }
    if (threadIdx.x == 0)
        atomicMax((unsigned*)&g_xmax_bits, __float_as_uint(red[0]));
}

__global__ void wscale_kernel(
    const float* __restrict__ Wgx, const float* __restrict__ Wgh,
    const float* __restrict__ Wix, const float* __restrict__ Wih,
    const float* __restrict__ Wfx, const float* __restrict__ Wfh,
    const float* __restrict__ Wox, const float* __restrict__ Woh,
    const float* __restrict__ bg,  const float* __restrict__ bi,
    const float* __restrict__ bf,  const float* __restrict__ bo)
{
    int n = blockIdx.x * blockDim.x + threadIdx.x;
    if (n >= NTOT) return;
    int j, g;
    decode_col(n, j, g);
    const float* sx = (g == 0) ? Wgx : (g == 1) ? Wix : (g == 2) ? Wfx : Wox;
    const float* sh = (g == 0) ? Wgh : (g == 1) ? Wih : (g == 2) ? Wfh : Woh;
    float mx = 0.0f, mh = 0.0f;
    for (int k = 0; k < DD; k++)      mx = fmaxf(mx, fabsf(sx[(size_t)k * HH + j]));
    for (int k = 0; k < HH; k++)      mh = fmaxf(mh, fabsf(sh[(size_t)k * HH + j]));
    g_wmx[n] = mx;
    g_wmh[n] = mh;
    const float* bb = (g == 0) ? bg : (g == 1) ? bi : (g == 2) ? bf : bo;
    g_bias[n] = bb[j];
}

__global__ void pack_wq_kernel(
    const float* __restrict__ Wgx, const float* __restrict__ Wgh,
    const float* __restrict__ Wix, const float* __restrict__ Wih,
    const float* __restrict__ Wfx, const float* __restrict__ Wfh,
    const float* __restrict__ Wox, const float* __restrict__ Woh)
{
    const long total = (long)NTOT * KTOT;
    for (long idx = (long)blockIdx.x * blockDim.x + threadIdx.x; idx < total;
         idx += (long)gridDim.x * blockDim.x) {
        int n = (int)(idx / KTOT);
        int k = (int)(idx % KTOT);
        int j, g;
        decode_col(n, j, g);
        float w, wm;
        if (k < DD) {
            const float* src = (g == 0) ? Wgx : (g == 1) ? Wix : (g == 2) ? Wfx : Wox;
            w = src[(size_t)k * HH + j];
            wm = g_wmx[n];
        } else {
            const float* src = (g == 0) ? Wgh : (g == 1) ? Wih : (g == 2) ? Wfh : Woh;
            w = src[(size_t)(k - DD) * HH + j];
            wm = g_wmh[n];
        }
        float s = fmaxf(wm, 1e-20f) / QLVL;
        int wq = __float2int_rn(w / s);
        wq = max(-16256, min(16256, wq));
        int hi, lo;
        split_q(wq, hi, lo);
        g_W8h[idx] = (int8_t)hi;
        g_W8l[idx] = (int8_t)lo;

        if (idx < NTOT) {
            float xmax = __uint_as_float(g_xmax_bits);
            float sxv = fmaxf(xmax, 1e-20f) / QLVL;
            g_scx[idx] = sxv * (fmaxf(g_wmx[idx], 1e-20f) / QLVL);
            g_sch[idx] = (1.0f / QLVL) * (fmaxf(g_wmh[idx], 1e-20f) / QLVL);
        }
        if (idx < (long)BB * HH) {
            g_h8h[0][idx] = 0; g_h8l[0][idx] = 0;
            g_h8h[1][idx] = 0; g_h8l[1][idx] = 0;
        }
    }
}

__global__ void pack_xq_kernel(const float* __restrict__ x)
{
    const float xmax = fmaxf(__uint_as_float(g_xmax_bits), 1e-20f);
    const float inv = QLVL / xmax;
    const long total = (long)TT * BB * DD;
    for (long idx = (long)blockIdx.x * blockDim.x + threadIdx.x; idx < total;
         idx += (long)gridDim.x * blockDim.x) {
        int t = (int)(idx / (BB * DD));
        int r = (int)(idx % (BB * DD));
        int b = r / DD;
        int d = r % DD;
        float v = x[((size_t)b * TT + t) * DD + d];
        int q = __float2int_rn(v * inv);
        q = max(-16256, min(16256, q));
        int hi, lo;
        split_q(q, hi, lo);
        g_x8h[idx] = (int8_t)hi;
        g_x8l[idx] = (int8_t)lo;
    }
}

// ---------------- grid barrier ----------------
__device__ __forceinline__ void grid_sync(unsigned target)
{
    __syncthreads();
    if (threadIdx.x == 0) {
        asm volatile("red.release.gpu.global.add.u32 [%0], %1;" :: "l"(&g_bar), "r"(1u) : "memory");
        unsigned v;
        do {
            asm volatile("ld.acquire.gpu.global.u32 %0, [%1];" : "=r"(v) : "l"(&g_bar) : "memory");
        } while (v < target);
    }
    __syncthreads();
}

__device__ __forceinline__ float sigf(float x) { return 1.0f / (1.0f + __expf(-x)); }
__device__ __forceinline__ float tanhfast(float x) { return 2.0f * sigf(2.0f * x) - 1.0f; }

// ---------------- A staging (h or x region), int8 hi/lo ----------------
__device__ __forceinline__ void stage_A(uint32_t sb, int t, int m0, int kb, int tid,
                                        const int8_t* __restrict__ h_hi,
                                        const int8_t* __restrict__ h_lo)
{
#pragma unroll
    for (int i = 0; i < 4; i++) {
        int ch  = tid + i * NTH;        // 0..1023
        int row = ch >> 3;              // 0..127
        int c16 = (ch & 7) * 16;
        const int8_t *ph, *pl;
        if (kb < 2) {
            size_t o = ((size_t)t * BB + (m0 + row)) * DD + kb * KBLK + c16;
            ph = g_x8h + o; pl = g_x8l + o;
        } else {
            size_t o = (size_t)(m0 + row) * HH + (kb - 2) * KBLK + c16;
            ph = h_hi + o; pl = h_lo + o;
        }
        uint32_t d = SW(row * 128 + c16);
        CP16(sb + OFF_AH + d, ph);
        CP16(sb + OFF_AL + d, pl);
    }
}

// ---------------- per-block compute: 128-K slab = 4 k32 groups, 3 imma terms ----------------
__device__ __forceinline__ void compute_block(uint32_t sbase, uint32_t sb, int kb,
                                              int lane, int m0w, int n0w,
                                              int P0[2][4][4], int P1[2][4][4])
{
    const int rA = m0w + (lane & 15);
    const int cX = (lane >> 4) * 16;
    const int rW = (kb << 6) + n0w + (lane & 15);

#pragma unroll
    for (int q = 0; q < 4; q++) {
        uint32_t Ah[2][4], Al[2][4];
#pragma unroll
        for (int mf = 0; mf < 2; mf++) {
            int off = (rA + mf * 16) * 128 + q * 32 + cX;
            LDSM_X4(Ah[mf][0], Ah[mf][1], Ah[mf][2], Ah[mf][3], sb + OFF_AH + SW(off));
            LDSM_X4(Al[mf][0], Al[mf][1], Al[mf][2], Al[mf][3], sb + OFF_AL + SW(off));
        }
        uint32_t Wh[4][2], Wl[4][2];
#pragma unroll
        for (int nn = 0; nn < 2; nn++) {
            int off = (rW + nn * 16) * 128 + q * 32 + cX;
            uint32_t r0, r1, r2, r3;
            LDSM_X4(r0, r1, r2, r3, sbase + OFF_WH + SW(off));
            Wh[nn * 2 + 0][0] = r0; Wh[nn * 2 + 0][1] = r2;
            Wh[nn * 2 + 1][0] = r1; Wh[nn * 2 + 1][1] = r3;
            LDSM_X4(r0, r1, r2, r3, sbase + OFF_WL + SW(off));
            Wl[nn * 2 + 0][0] = r0; Wl[nn * 2 + 0][1] = r2;
            Wl[nn * 2 + 1][0] = r1; Wl[nn * 2 + 1][1] = r3;
        }
#pragma unroll
        for (int mf = 0; mf < 2; mf++)
#pragma unroll
            for (int nf = 0; nf < 4; nf++) {
                MMA_S8(P0[mf][nf], Ah[mf], Wh[nf]);
                MMA_S8(P1[mf][nf], Ah[mf], Wl[nf]);
                MMA_S8(P1[mf][nf], Al[mf], Wh[nf]);
            }
    }
}

// ---------------- persistent LSTM kernel ----------------
__global__ void __launch_bounds__(NTH, 1) lstm_i8_kernel(
    const float* __restrict__ Wph, const float* __restrict__ bp, float* __restrict__ out)
{
    extern __shared__ char smem[];
    const uint32_t sbase = smem_to_u32(smem);
    const int tid  = threadIdx.x;
    const int wid  = tid >> 5;
    const int lane = tid & 31;
    const int m0w  = (wid >> 1) * 32;
    const int n0w  = (wid & 1) * 32;
    const int mt   = blockIdx.x >> 6;     // 0..1
    const int nt   = blockIdx.x & 63;     // 0..63
    const int m0   = mt * 128;
    const int n0   = nt * 64;
    const int j0   = nt * 16 + (n0w >> 2);
    const int gid  = lane >> 2;
    const int tid4 = lane & 3;

    // ---- load resident W (int8 hi/lo, rows r = kb*64 + nl, SW128) ----
#pragma unroll
    for (int i = 0; i < 20; i++) {
        int ch  = tid + i * NTH;          // 0..5119
        int r   = ch >> 3;                // 0..639
        int c16 = (ch & 7) * 16;
        int nl  = r & 63;
        int kb  = r >> 6;
        size_t so = (size_t)(n0 + nl) * KTOT + kb * KBLK + c16;
        uint32_t d = SW(r * 128 + c16);
        CP16(sbase + OFF_WH + d, g_W8h + so);
        CP16(sbase + OFF_WL + d, g_W8l + so);
    }
    // ---- scale/bias tables ----
    float* tscx  = (float*)(smem + OFF_TBL);
    float* tsch  = tscx + 64;
    float* tbias = tsch + 64;
    if (tid < 64) {
        tscx[tid]  = g_scx[n0 + tid];
        tsch[tid]  = g_sch[n0 + tid];
        tbias[tid] = g_bias[n0 + tid];
    }
    CP_COMMIT();
    CP_WAIT0();
    __syncthreads();

    float cst[2][2][2];
#pragma unroll
    for (int a = 0; a < 2; a++)
#pragma unroll
        for (int b = 0; b < 2; b++)
#pragma unroll
            for (int cdx = 0; cdx < 2; cdx++) cst[a][b][cdx] = 0.0f;

    for (int t = 0; t < TT; t++) {
        const int rb = t & 1;
        const int wb = rb ^ 1;
        const int8_t* hrd_hi = g_h8h[rb];
        const int8_t* hrd_lo = g_h8l[rb];
        int8_t* hwr_hi = g_h8h[wb];
        int8_t* hwr_lo = g_h8l[wb];

        int P0[2][4][4], P1[2][4][4];
#pragma unroll
        for (int mf = 0; mf < 2; mf++)
#pragma unroll
            for (int nf = 0; nf < 4; nf++)
#pragma unroll
                for (int e = 0; e < 4; e++) { P0[mf][nf][e] = 0; P1[mf][nf][e] = 0; }
        float fpre[2][4][4];

        const uint32_t ast = sbase + OFF_AST;
        stage_A(ast,              t, m0, 0, tid, hrd_hi, hrd_lo); CP_COMMIT();
        stage_A(ast + STG_STRIDE, t, m0, 1, tid, hrd_hi, hrd_lo); CP_COMMIT();

        for (int kc = 0; kc < NKB; kc++) {
            if (kc < NKB - 1) CP_WAIT1(); else CP_WAIT0();
            __syncthreads();
            const uint32_t sb = ast + (kc & 1) * STG_STRIDE;
            compute_block(sbase, sb, kc, lane, m0w, n0w, P0, P1);
            __syncthreads();
            if (kc + 2 < NKB) {
                stage_A(sb, t, m0, kc + 2, tid, hrd_hi, hrd_lo);
                CP_COMMIT();
            }
            if (kc == 1) {
                // x-region done: convert to fp32 partial with x scales, reset accums
#pragma unroll
                for (int mf = 0; mf < 2; mf++)
#pragma unroll
                    for (int nf = 0; nf < 4; nf++)
#pragma unroll
                        for (int e = 0; e < 4; e++) {
                            int col = n0w + nf * 8 + tid4 * 2 + (e & 1);
                            fpre[mf][nf][e] =
                                ((float)P0[mf][nf][e] * 16384.0f +
                                 (float)P1[mf][nf][e] * 128.0f) * tscx[col];
                            P0[mf][nf][e] = 0;
                            P1[mf][nf][e] = 0;
                        }
            }
        }

        // ---- gate math + state update ----
#pragma unroll
        for (int mf = 0; mf < 2; mf++)
#pragma unroll
            for (int hr = 0; hr < 2; hr++) {
                const int m = m0 + m0w + mf * 16 + gid + hr * 8;
#pragma unroll
                for (int u2 = 0; u2 < 2; u2++) {
                    float p[4];
#pragma unroll
                    for (int g = 0; g < 4; g++) {
                        int nf = u2 * 2 + (g >> 1);
                        int e  = hr * 2 + (g & 1);
                        int col = n0w + nf * 8 + tid4 * 2 + (g & 1);
                        p[g] = fpre[mf][nf][e] +
                               ((float)P0[mf][nf][e] * 16384.0f +
                                (float)P1[mf][nf][e] * 128.0f) * tsch[col] + tbias[col];
                    }
                    float gt = tanhfast(p[0]);
                    float it = sigf(p[1]);
                    float ft = sigf(p[2]);
                    float ot = sigf(p[3]);
                    float cn = gt * it + cst[mf][hr][u2] * ft;
                    cst[mf][hr][u2] = cn;
                    float hv = tanhfast(cn) * ot;
                    const int j = j0 + u2 * 4 + tid4;
                    size_t o = (size_t)m * HH + j;
                    int hq = __float2int_rn(hv * QLVL);
                    int hhi, hlo;
                    split_q(hq, hhi, hlo);
                    hwr_hi[o] = (int8_t)hhi;
                    hwr_lo[o] = (int8_t)hlo;
                    if (t == TT - 1) g_hf[o] = hv;
                }
            }

        grid_sync((unsigned)(t + 1) * GRID);
    }

    // ---- final projection: out[b][cc] = g_hf[b] . Wph[:,cc] + bp[cc] ----
    {
        const int gidx = blockIdx.x * NTH + tid;   // 32768 = 256 x 128
        const int b  = gidx >> 7;
        const int cc = gidx & 127;
        const float* hrow = g_hf + (size_t)b * HH;
        float s = 0.0f;
#pragma unroll 8
        for (int k = 0; k < HH; k++) s += hrow[k] * Wph[(size_t)k * CCC + cc];
        out[gidx] = s + bp[cc];
    }
}

// ---------------- launch ----------------
extern "C" void kernel_launch(void* const* d_in, const int* in_sizes, int n_in,
                              void* d_out, int out_size)
{
    (void)in_sizes; (void)n_in; (void)out_size;
    const float* x   = (const float*)d_in[0];
    const float* Wgx = (const float*)d_in[1];
    const float* Wgh = (const float*)d_in[2];
    const float* bg  = (const float*)d_in[3];
    const float* Wix = (const float*)d_in[4];
    const float* Wih = (const float*)d_in[5];
    const float* bi  = (const float*)d_in[6];
    const float* Wfx = (const float*)d_in[7];
    const float* Wfh = (const float*)d_in[8];
    const float* bf  = (const float*)d_in[9];
    const float* Wox = (const float*)d_in[10];
    const float* Woh = (const float*)d_in[11];
    const float* bo  = (const float*)d_in[12];
    const float* Wph = (const float*)d_in[13];
    const float* bp  = (const float*)d_in[14];

    cudaFuncSetAttribute(lstm_i8_kernel, cudaFuncAttributeMaxDynamicSharedMemorySize, SMEM_TOTAL);

    init0_kernel<<<1, 32>>>();
    xmax_kernel<<<256, 256>>>(x);
    wscale_kernel<<<16, 256>>>(Wgx, Wgh, Wix, Wih, Wfx, Wfh, Wox, Woh, bg, bi, bf, bo);
    pack_wq_kernel<<<512, 256>>>(Wgx, Wgh, Wix, Wih, Wfx, Wfh, Wox, Woh);
    pack_xq_kernel<<<1024, 256>>>(x);
    lstm_i8_kernel<<<GRID, NTH, SMEM_TOTAL>>>(Wph, bp, (float*)d_out);
}

// round 11
// speedup vs baseline: 2.2644x; 2.2644x over previous
#include <cuda_runtime.h>
#include <cuda_bf16.h>
#include <math.h>
#include <stdint.h>

// LSTM B=256,T=512,D=256,H=1024,C=128.
// Persistent kernel on mma.sync bf16 (bf16x3 split => ~fp32 accuracy), fp32 accum.
// 128 CTAs = 2 Mtiles(128) x 64 Ntiles(64); grid barrier per timestep.
// R6: 4-stage cp.async pipeline, 1 sync/slab, barrier-overlapped prefetch.

#define BB   256
#define TT   512
#define DD   256
#define HH   1024
#define CCC  128
#define KTOT 1280
#define NTOT 4096
#define GRID 128
#define NTH  256
#define KBLK 64
#define NKB  (KTOT / KBLK)   // 20

// dynamic smem: FOUR stages of {A_hi 16K, A_lo 16K, W_hi 8K, W_lo 8K}
#define STG_STRIDE 49152
#define OFF_A_HI   0
#define OFF_A_LO   16384
#define OFF_W_HI   32768
#define OFF_W_LO   40960
#define NSTG       4
#define SMEM_TOTAL (NSTG * STG_STRIDE)   // 196608

#define SW(o) ((o) ^ (((o) >> 3) & 0x70))

// ---------------- device globals ----------------
__device__ __nv_bfloat16 g_Whi[(size_t)NTOT * KTOT];
__device__ __nv_bfloat16 g_Wlo[(size_t)NTOT * KTOT];
__device__ float         g_bcat[NTOT];
__device__ __nv_bfloat16 g_xhi[(size_t)TT * BB * DD];
__device__ __nv_bfloat16 g_xlo[(size_t)TT * BB * DD];
__device__ __nv_bfloat16 g_hhi[2][BB * HH];   // double-buffered across steps
__device__ __nv_bfloat16 g_hlo[2][BB * HH];
__device__ float         g_hf[BB * HH];
__device__ unsigned      g_bar;

// ---------------- PTX helpers ----------------
__device__ __forceinline__ uint32_t smem_to_u32(const void* p) {
    uint32_t a;
    asm("{ .reg .u64 t; cvta.to.shared.u64 t, %1; cvt.u32.u64 %0, t; }" : "=r"(a) : "l"(p));
    return a;
}

#define CP16(dst, src) \
    asm volatile("cp.async.cg.shared.global [%0], [%1], 16;" :: "r"(dst), "l"(src) : "memory")
#define CP_COMMIT() asm volatile("cp.async.commit_group;" ::: "memory")
#define CP_WAIT0()  asm volatile("cp.async.wait_group 0;" ::: "memory")
#define CP_WAIT1()  asm volatile("cp.async.wait_group 1;" ::: "memory")
#define CP_WAIT2()  asm volatile("cp.async.wait_group 2;" ::: "memory")

#define LDSM_X4(r0, r1, r2, r3, addr) \
    asm volatile("ldmatrix.sync.aligned.m8n8.x4.shared.b16 {%0,%1,%2,%3}, [%4];" \
                 : "=r"(r0), "=r"(r1), "=r"(r2), "=r"(r3) : "r"(addr))

#define MMA_BF16(c, a, b) \
    asm volatile("mma.sync.aligned.m16n8k16.row.col.f32.bf16.bf16.f32 " \
                 "{%0,%1,%2,%3},{%4,%5,%6,%7},{%8,%9},{%0,%1,%2,%3};" \
                 : "+f"((c)[0]), "+f"((c)[1]), "+f"((c)[2]), "+f"((c)[3]) \
                 : "r"((a)[0]), "r"((a)[1]), "r"((a)[2]), "r"((a)[3]), \
                   "r"((b)[0]), "r"((b)[1]))

// ---------------- column interleave mapping ----------------
// Within each 32-col warp tile: col(u,g) = 16*(u>>2) + 8*(g>>1) + 2*(u&3) + (g&1)
// => u = ((o>>4)<<2) + ((o>>1)&3),  g = ((o>>3)&1)*2 + (o&1)
// Global: n = w32*32 + o,  hidden j = w32*8 + u.

// ---------------- init kernels ----------------
__global__ void pack_w_kernel(
    const float* __restrict__ Wgx, const float* __restrict__ Wgh,
    const float* __restrict__ Wix, const float* __restrict__ Wih,
    const float* __restrict__ Wfx, const float* __restrict__ Wfh,
    const float* __restrict__ Wox, const float* __restrict__ Woh,
    const float* __restrict__ bg,  const float* __restrict__ bi,
    const float* __restrict__ bf,  const float* __restrict__ bo)
{
    const long total = (long)NTOT * KTOT;
    for (long idx = (long)blockIdx.x * blockDim.x + threadIdx.x; idx < total;
         idx += (long)gridDim.x * blockDim.x) {
        int n = (int)(idx / KTOT);
        int k = (int)(idx % KTOT);
        int o = n & 31;
        int w32 = n >> 5;
        int u = ((o >> 4) << 2) + ((o >> 1) & 3);
        int g = ((o >> 3) & 1) * 2 + (o & 1);
        int j = w32 * 8 + u;
        float w;
        if (k < DD) {
            const float* src = (g == 0) ? Wgx : (g == 1) ? Wix : (g == 2) ? Wfx : Wox;
            w = src[(size_t)k * HH + j];
        } else {
            const float* src = (g == 0) ? Wgh : (g == 1) ? Wih : (g == 2) ? Wfh : Woh;
            w = src[(size_t)(k - DD) * HH + j];
        }
        __nv_bfloat16 hi = __float2bfloat16(w);
        g_Whi[idx] = hi;
        g_Wlo[idx] = __float2bfloat16(w - __bfloat162float(hi));

        if (idx < NTOT) {
            int nb  = (int)idx;
            int ob  = nb & 31;
            int wb  = nb >> 5;
            int ub  = ((ob >> 4) << 2) + ((ob >> 1) & 3);
            int gb  = ((ob >> 3) & 1) * 2 + (ob & 1);
            int jb  = wb * 8 + ub;
            const float* bsrc = (gb == 0) ? bg : (gb == 1) ? bi : (gb == 2) ? bf : bo;
            g_bcat[nb] = bsrc[jb];
        }
        if (idx < (long)BB * HH) {
            g_hhi[0][idx] = __float2bfloat16(0.0f);
            g_hlo[0][idx] = __float2bfloat16(0.0f);
            g_hhi[1][idx] = __float2bfloat16(0.0f);
            g_hlo[1][idx] = __float2bfloat16(0.0f);
        }
        if (idx == 0) g_bar = 0u;
    }
}

__global__ void pack_x_kernel(const float* __restrict__ x)
{
    const long total = (long)TT * BB * DD;
    for (long idx = (long)blockIdx.x * blockDim.x + threadIdx.x; idx < total;
         idx += (long)gridDim.x * blockDim.x) {
        int t = (int)(idx / (BB * DD));
        int r = (int)(idx % (BB * DD));
        int b = r / DD;
        int d = r % DD;
        float v = x[((size_t)b * TT + t) * DD + d];
        __nv_bfloat16 hi = __float2bfloat16(v);
        g_xhi[idx] = hi;
        g_xlo[idx] = __float2bfloat16(v - __bfloat162float(hi));
    }
}

// ---------------- grid barrier ----------------
__device__ __forceinline__ void grid_sync(unsigned target)
{
    __syncthreads();
    if (threadIdx.x == 0) {
        asm volatile("red.release.gpu.global.add.u32 [%0], %1;" :: "l"(&g_bar), "r"(1u) : "memory");
        unsigned v;
        do {
            asm volatile("ld.acquire.gpu.global.u32 %0, [%1];" : "=r"(v) : "l"(&g_bar) : "memory");
        } while (v < target);
    }
    __syncthreads();
}

__device__ __forceinline__ float sigf(float x) { return 1.0f / (1.0f + __expf(-x)); }
__device__ __forceinline__ float tanhfast(float x) { return 2.0f * sigf(2.0f * x) - 1.0f; }

// ---------------- staging: gmem -> smem via cp.async ----------------
__device__ __forceinline__ void stage_load(uint32_t sb, int t, int m0, int n0,
                                           int k0, int tid,
                                           const __nv_bfloat16* __restrict__ hhi,
                                           const __nv_bfloat16* __restrict__ hlo)
{
#pragma unroll
    for (int i = 0; i < 4; i++) {
        int idx = tid + i * NTH;       // 0..1023
        int row = idx >> 3;            // 0..127
        int q   = idx & 7;
        const __nv_bfloat16 *ph, *pl;
        if (k0 < DD) {
            size_t o = ((size_t)t * BB + (m0 + row)) * DD + k0 + q * 8;
            ph = g_xhi + o; pl = g_xlo + o;
        } else {
            size_t o = (size_t)(m0 + row) * HH + (k0 - DD) + q * 8;
            ph = hhi + o; pl = hlo + o;
        }
        uint32_t d = SW(row * 128 + q * 16);
        CP16(sb + OFF_A_HI + d, ph);
        CP16(sb + OFF_A_LO + d, pl);
    }
#pragma unroll
    for (int i = 0; i < 2; i++) {
        int idx = tid + i * NTH;       // 0..511
        int row = idx >> 3;            // 0..63
        int q   = idx & 7;
        size_t o = (size_t)(n0 + row) * KTOT + k0 + q * 8;
        uint32_t d = SW(row * 128 + q * 16);
        CP16(sb + OFF_W_HI + d, g_Whi + o);
        CP16(sb + OFF_W_LO + d, g_Wlo + o);
    }
}

// ---------------- per-stage compute: 64-K slab, 3 split terms ----------------
__device__ __forceinline__ void compute_stage(uint32_t sb, int lane, int m0w, int n0w,
                                              float acc[2][4][4])
{
    const int rowA = m0w + (lane & 15);
    const int colA = (lane >> 4) * 16;
    const int rowB = n0w + (lane & 15);
    const int colB = (lane >> 4) * 16;

#pragma unroll
    for (int k16 = 0; k16 < 4; k16++) {
        uint32_t ahi[2][4], alo[2][4];
#pragma unroll
        for (int mf = 0; mf < 2; mf++) {
            int off = (rowA + mf * 16) * 128 + colA + k16 * 32;
            LDSM_X4(ahi[mf][0], ahi[mf][1], ahi[mf][2], ahi[mf][3], sb + OFF_A_HI + SW(off));
            LDSM_X4(alo[mf][0], alo[mf][1], alo[mf][2], alo[mf][3], sb + OFF_A_LO + SW(off));
        }
        // W is [n][k] k-contiguous: NON-trans ldmatrix over n-rows yields the
        // exact mma.sync B fragment.
        uint32_t whi[4][2], wlo[4][2];
#pragma unroll
        for (int nn = 0; nn < 2; nn++) {
            int off = (rowB + nn * 16) * 128 + colB + k16 * 32;
            uint32_t r0, r1, r2, r3;
            LDSM_X4(r0, r1, r2, r3, sb + OFF_W_HI + SW(off));
            whi[nn * 2 + 0][0] = r0; whi[nn * 2 + 0][1] = r2;
            whi[nn * 2 + 1][0] = r1; whi[nn * 2 + 1][1] = r3;
            LDSM_X4(r0, r1, r2, r3, sb + OFF_W_LO + SW(off));
            wlo[nn * 2 + 0][0] = r0; wlo[nn * 2 + 0][1] = r2;
            wlo[nn * 2 + 1][0] = r1; wlo[nn * 2 + 1][1] = r3;
        }
#pragma unroll
        for (int mf = 0; mf < 2; mf++)
#pragma unroll
            for (int nf = 0; nf < 4; nf++) {
                MMA_BF16(acc[mf][nf], ahi[mf], whi[nf]);
                MMA_BF16(acc[mf][nf], ahi[mf], wlo[nf]);
                MMA_BF16(acc[mf][nf], alo[mf], whi[nf]);
            }
    }
}

// ---------------- persistent LSTM kernel ----------------
__global__ void __launch_bounds__(NTH, 1) lstm_mma_kernel(
    const float* __restrict__ Wph, const float* __restrict__ bp, float* __restrict__ out)
{
    extern __shared__ char smem[];
    const uint32_t sbase = smem_to_u32(smem);
    const int tid  = threadIdx.x;
    const int wid  = tid >> 5;
    const int lane = tid & 31;
    const int m0w  = (wid >> 1) * 32;
    const int n0w  = (wid & 1) * 32;
    const int mt   = blockIdx.x >> 6;     // 0..1
    const int nt   = blockIdx.x & 63;     // 0..63
    const int m0   = mt * 128;
    const int n0   = nt * 64;
    const int j0   = nt * 16 + (n0w >> 2);
    const int gid  = lane >> 2;
    const int tid4 = lane & 3;

    // per-thread bias for owned (u2, gate) cells
    float biasr[2][4];
#pragma unroll
    for (int u2 = 0; u2 < 2; u2++)
#pragma unroll
        for (int g = 0; g < 4; g++) {
            int o = (u2 * 2 + (g >> 1)) * 8 + tid4 * 2 + (g & 1);
            biasr[u2][g] = g_bcat[n0 + n0w + o];
        }

    // c-state in registers: [mf][hr][u2]
    float cst[2][2][2];
#pragma unroll
    for (int a = 0; a < 2; a++)
#pragma unroll
        for (int b = 0; b < 2; b++)
#pragma unroll
            for (int cdx = 0; cdx < 2; cdx++) cst[a][b][cdx] = 0.0f;

    // stage buffers: buf s at sbase + s*STG_STRIDE; slab kc -> buf kc&3
#define SBUF(s) (sbase + (uint32_t)(s) * STG_STRIDE)

    // prime: slabs 0,1 of t=0 (x region only; h buffer 0 is zeros anyway)
    stage_load(SBUF(0), 0, m0, n0, 0 * KBLK, tid, g_hhi[0], g_hlo[0]); CP_COMMIT();
    stage_load(SBUF(1), 0, m0, n0, 1 * KBLK, tid, g_hhi[0], g_hlo[0]); CP_COMMIT();

    for (int t = 0; t < TT; t++) {
        const int rb = t & 1;           // read h buffer
        const int wb = rb ^ 1;          // write h buffer
        const __nv_bfloat16* hrd_hi = g_hhi[rb];
        const __nv_bfloat16* hrd_lo = g_hlo[rb];

        float acc[2][4][4];
#pragma unroll
        for (int mf = 0; mf < 2; mf++)
#pragma unroll
            for (int nf = 0; nf < 4; nf++)
#pragma unroll
                for (int e = 0; e < 4; e++) acc[mf][nf][e] = 0.0f;

        // first h-dependent slab, immediately after the barrier released us
        stage_load(SBUF(2), t, m0, n0, 2 * KBLK, tid, hrd_hi, hrd_lo); CP_COMMIT();

        // main pipeline: at iter kc, groups {kc, kc+1, kc+2} are in flight
        for (int kc = 0; kc < NKB - 2; kc++) {       // kc = 0..17
            CP_WAIT2();
            __syncthreads();
            compute_stage(SBUF(kc & 3), lane, m0w, n0w, acc);
            if (kc < NKB - 3) {                      // store slab kc+3 (<= 19)
                stage_load(SBUF((kc + 3) & 3), t, m0, n0, (kc + 3) * KBLK, tid,
                           hrd_hi, hrd_lo);
                CP_COMMIT();
            }
        }
        // kc = 18
        CP_WAIT1(); __syncthreads();
        compute_stage(SBUF(18 & 3), lane, m0w, n0w, acc);
        // kc = 19
        CP_WAIT0(); __syncthreads();
        compute_stage(SBUF(19 & 3), lane, m0w, n0w, acc);

        // gate math + state update, all in-register
#pragma unroll
        for (int mf = 0; mf < 2; mf++)
#pragma unroll
            for (int hr = 0; hr < 2; hr++) {
                const int m = m0 + m0w + mf * 16 + gid + hr * 8;
#pragma unroll
                for (int u2 = 0; u2 < 2; u2++) {
                    float pg = acc[mf][u2 * 2 + 0][hr * 2 + 0] + biasr[u2][0];
                    float pi = acc[mf][u2 * 2 + 0][hr * 2 + 1] + biasr[u2][1];
                    float pf = acc[mf][u2 * 2 + 1][hr * 2 + 0] + biasr[u2][2];
                    float po = acc[mf][u2 * 2 + 1][hr * 2 + 1] + biasr[u2][3];
                    float gt = tanhfast(pg);
                    float it = sigf(pi);
                    float ft = sigf(pf);
                    float ot = sigf(po);
                    float cn = gt * it + cst[mf][hr][u2] * ft;
                    cst[mf][hr][u2] = cn;
                    float hv = tanhfast(cn) * ot;
                    const int j = j0 + u2 * 4 + tid4;
                    size_t o = (size_t)m * HH + j;
                    __nv_bfloat16 hh = __float2bfloat16(hv);
                    g_hhi[wb][o] = hh;
                    g_hlo[wb][o] = __float2bfloat16(hv - __bfloat162float(hh));
                    if (t == TT - 1) g_hf[o] = hv;
                }
            }

        // all warps done with the stage buffers before we overwrite buf0/buf1
        __syncthreads();

        // prefetch t+1 slabs 0,1 (x region, no h dependency) BEFORE the barrier
        if (t + 1 < TT) {
            stage_load(SBUF(0), t + 1, m0, n0, 0 * KBLK, tid, hrd_hi, hrd_lo); CP_COMMIT();
            stage_load(SBUF(1), t + 1, m0, n0, 1 * KBLK, tid, hrd_hi, hrd_lo); CP_COMMIT();
        }

        grid_sync((unsigned)(t + 1) * GRID);
    }

    // final projection: out[b][cc] = g_hf[b] . Wph[:,cc] + bp[cc]
    {
        const int gidx = blockIdx.x * NTH + tid;   // 0..32767 = 256 x 128
        const int b  = gidx >> 7;
        const int cc = gidx & 127;
        const float* hrow = g_hf + (size_t)b * HH;
        float s = 0.0f;
#pragma unroll 8
        for (int k = 0; k < HH; k++) s += hrow[k] * Wph[(size_t)k * CCC + cc];
        out[gidx] = s + bp[cc];
    }
#undef SBUF
}

// ---------------- launch ----------------
extern "C" void kernel_launch(void* const* d_in, const int* in_sizes, int n_in,
                              void* d_out, int out_size)
{
    (void)in_sizes; (void)n_in; (void)out_size;
    const float* x   = (const float*)d_in[0];
    const float* Wgx = (const float*)d_in[1];
    const float* Wgh = (const float*)d_in[2];
    const float* bg  = (const float*)d_in[3];
    const float* Wix = (const float*)d_in[4];
    const float* Wih = (const float*)d_in[5];
    const float* bi  = (const float*)d_in[6];
    const float* Wfx = (const float*)d_in[7];
    const float* Wfh = (const float*)d_in[8];
    const float* bf  = (const float*)d_in[9];
    const float* Wox = (const float*)d_in[10];
    const float* Woh = (const float*)d_in[11];
    const float* bo  = (const float*)d_in[12];
    const float* Wph = (const float*)d_in[13];
    const float* bp  = (const float*)d_in[14];

    cudaFuncSetAttribute(lstm_mma_kernel, cudaFuncAttributeMaxDynamicSharedMemorySize, SMEM_TOTAL);

    pack_w_kernel<<<512, 256>>>(Wgx, Wgh, Wix, Wih, Wfx, Wfh, Wox, Woh, bg, bi, bf, bo);
    pack_x_kernel<<<2048, 256>>>(x);
    lstm_mma_kernel<<<GRID, NTH, SMEM_TOTAL>>>(Wph, bp, (float*)d_out);
}

// round 12
// speedup vs baseline: 3.1364x; 1.3851x over previous
#include <cuda_runtime.h>
#include <cuda_fp16.h>
#include <math.h>
#include <stdint.h>

// LSTM B=256,T=512,D=256,H=1024,C=128.
// Persistent kernel on mma.sync fp16 (W split hi/lo fp16x2, A single fp16),
// fp32 accum: 2 MMA terms per tile. 128 CTAs = 2 Mtiles(128) x 64 Ntiles(64).
// 4-stage cp.async pipeline, grid barrier per timestep, h double-buffered.

#define BB   256
#define TT   512
#define DD   256
#define HH   1024
#define CCC  128
#define KTOT 1280
#define NTOT 4096
#define GRID 128
#define NTH  256
#define KBLK 64
#define NKB  (KTOT / KBLK)   // 20

// dynamic smem: FOUR stages of {A 16K, W_hi 8K, W_lo 8K}
#define STG_STRIDE 32768
#define OFF_A      0
#define OFF_W_HI   16384
#define OFF_W_LO   24576
#define NSTG       4
#define SMEM_TOTAL (NSTG * STG_STRIDE)   // 131072

#define SW(o) ((o) ^ (((o) >> 3) & 0x70))

// ---------------- device globals ----------------
__device__ __half g_Whi[(size_t)NTOT * KTOT];
__device__ __half g_Wlo[(size_t)NTOT * KTOT];
__device__ float  g_bcat[NTOT];
__device__ __half g_x16[(size_t)TT * BB * DD];
__device__ __half g_h16[2][BB * HH];   // double-buffered across steps
__device__ float  g_hf[BB * HH];
__device__ unsigned g_bar;

// ---------------- PTX helpers ----------------
__device__ __forceinline__ uint32_t smem_to_u32(const void* p) {
    uint32_t a;
    asm("{ .reg .u64 t; cvta.to.shared.u64 t, %1; cvt.u32.u64 %0, t; }" : "=r"(a) : "l"(p));
    return a;
}

#define CP16(dst, src) \
    asm volatile("cp.async.cg.shared.global [%0], [%1], 16;" :: "r"(dst), "l"(src) : "memory")
#define CP_COMMIT() asm volatile("cp.async.commit_group;" ::: "memory")
#define CP_WAIT0()  asm volatile("cp.async.wait_group 0;" ::: "memory")
#define CP_WAIT1()  asm volatile("cp.async.wait_group 1;" ::: "memory")
#define CP_WAIT2()  asm volatile("cp.async.wait_group 2;" ::: "memory")

#define LDSM_X4(r0, r1, r2, r3, addr) \
    asm volatile("ldmatrix.sync.aligned.m8n8.x4.shared.b16 {%0,%1,%2,%3}, [%4];" \
                 : "=r"(r0), "=r"(r1), "=r"(r2), "=r"(r3) : "r"(addr))

#define MMA_F16(c, a, b) \
    asm volatile("mma.sync.aligned.m16n8k16.row.col.f32.f16.f16.f32 " \
                 "{%0,%1,%2,%3},{%4,%5,%6,%7},{%8,%9},{%0,%1,%2,%3};" \
                 : "+f"((c)[0]), "+f"((c)[1]), "+f"((c)[2]), "+f"((c)[3]) \
                 : "r"((a)[0]), "r"((a)[1]), "r"((a)[2]), "r"((a)[3]), \
                   "r"((b)[0]), "r"((b)[1]))

// ---------------- column interleave mapping ----------------
// Within each 32-col warp tile: col(u,g) = 16*(u>>2) + 8*(g>>1) + 2*(u&3) + (g&1)
// => u = ((o>>4)<<2) + ((o>>1)&3),  g = ((o>>3)&1)*2 + (o&1)
// Global: n = w32*32 + o,  hidden j = w32*8 + u.

// ---------------- init kernels ----------------
__global__ void pack_w_kernel(
    const float* __restrict__ Wgx, const float* __restrict__ Wgh,
    const float* __restrict__ Wix, const float* __restrict__ Wih,
    const float* __restrict__ Wfx, const float* __restrict__ Wfh,
    const float* __restrict__ Wox, const float* __restrict__ Woh,
    const float* __restrict__ bg,  const float* __restrict__ bi,
    const float* __restrict__ bf,  const float* __restrict__ bo)
{
    const long total = (long)NTOT * KTOT;
    for (long idx = (long)blockIdx.x * blockDim.x + threadIdx.x; idx < total;
         idx += (long)gridDim.x * blockDim.x) {
        int n = (int)(idx / KTOT);
        int k = (int)(idx % KTOT);
        int o = n & 31;
        int w32 = n >> 5;
        int u = ((o >> 4) << 2) + ((o >> 1) & 3);
        int g = ((o >> 3) & 1) * 2 + (o & 1);
        int j = w32 * 8 + u;
        float w;
        if (k < DD) {
            const float* src = (g == 0) ? Wgx : (g == 1) ? Wix : (g == 2) ? Wfx : Wox;
            w = src[(size_t)k * HH + j];
        } else {
            const float* src = (g == 0) ? Wgh : (g == 1) ? Wih : (g == 2) ? Wfh : Woh;
            w = src[(size_t)(k - DD) * HH + j];
        }
        __half hi = __float2half_rn(w);
        g_Whi[idx] = hi;
        g_Wlo[idx] = __float2half_rn(w - __half2float(hi));

        if (idx < NTOT) {
            int nb  = (int)idx;
            int ob  = nb & 31;
            int wb  = nb >> 5;
            int ub  = ((ob >> 4) << 2) + ((ob >> 1) & 3);
            int gb  = ((ob >> 3) & 1) * 2 + (ob & 1);
            int jb  = wb * 8 + ub;
            const float* bsrc = (gb == 0) ? bg : (gb == 1) ? bi : (gb == 2) ? bf : bo;
            g_bcat[nb] = bsrc[jb];
        }
        if (idx < (long)BB * HH) {
            g_h16[0][idx] = __float2half_rn(0.0f);
            g_h16[1][idx] = __float2half_rn(0.0f);
        }
        if (idx == 0) g_bar = 0u;
    }
}

__global__ void pack_x_kernel(const float* __restrict__ x)
{
    const long total = (long)TT * BB * DD;
    for (long idx = (long)blockIdx.x * blockDim.x + threadIdx.x; idx < total;
         idx += (long)gridDim.x * blockDim.x) {
        int t = (int)(idx / (BB * DD));
        int r = (int)(idx % (BB * DD));
        int b = r / DD;
        int d = r % DD;
        g_x16[idx] = __float2half_rn(x[((size_t)b * TT + t) * DD + d]);
    }
}

// ---------------- grid barrier ----------------
__device__ __forceinline__ void grid_sync(unsigned target)
{
    __syncthreads();
    if (threadIdx.x == 0) {
        asm volatile("red.release.gpu.global.add.u32 [%0], %1;" :: "l"(&g_bar), "r"(1u) : "memory");
        unsigned v;
        do {
            asm volatile("ld.acquire.gpu.global.u32 %0, [%1];" : "=r"(v) : "l"(&g_bar) : "memory");
        } while (v < target);
    }
    __syncthreads();
}

__device__ __forceinline__ float sigf(float x) { return 1.0f / (1.0f + __expf(-x)); }
__device__ __forceinline__ float tanhfast(float x) { return 2.0f * sigf(2.0f * x) - 1.0f; }

// ---------------- staging: gmem -> smem via cp.async ----------------
// A: 128 rows x 64 fp16 = 128B/row -> 1024 x 16B chunks? (128*8=1024) -> 4/thread
// W: 64 rows x 128B x2 arrays -> 512 chunks each -> 2/thread each
__device__ __forceinline__ void stage_load(uint32_t sb, int t, int m0, int n0,
                                           int k0, int tid,
                                           const __half* __restrict__ hrd)
{
#pragma unroll
    for (int i = 0; i < 4; i++) {
        int idx = tid + i * NTH;       // 0..1023
        int row = idx >> 3;            // 0..127
        int q   = idx & 7;
        const __half* ph;
        if (k0 < DD) {
            ph = g_x16 + ((size_t)t * BB + (m0 + row)) * DD + k0 + q * 8;
        } else {
            ph = hrd + (size_t)(m0 + row) * HH + (k0 - DD) + q * 8;
        }
        CP16(sb + OFF_A + SW(row * 128 + q * 16), ph);
    }
#pragma unroll
    for (int i = 0; i < 2; i++) {
        int idx = tid + i * NTH;       // 0..511
        int row = idx >> 3;            // 0..63
        int q   = idx & 7;
        size_t o = (size_t)(n0 + row) * KTOT + k0 + q * 8;
        uint32_t d = SW(row * 128 + q * 16);
        CP16(sb + OFF_W_HI + d, g_Whi + o);
        CP16(sb + OFF_W_LO + d, g_Wlo + o);
    }
}

// ---------------- per-stage compute: 64-K slab, 2 terms ----------------
__device__ __forceinline__ void compute_stage(uint32_t sb, int lane, int m0w, int n0w,
                                              float acc[2][4][4])
{
    const int rowA = m0w + (lane & 15);
    const int colA = (lane >> 4) * 16;
    const int rowB = n0w + (lane & 15);
    const int colB = (lane >> 4) * 16;

#pragma unroll
    for (int k16 = 0; k16 < 4; k16++) {
        uint32_t a[2][4];
#pragma unroll
        for (int mf = 0; mf < 2; mf++) {
            int off = (rowA + mf * 16) * 128 + colA + k16 * 32;
            LDSM_X4(a[mf][0], a[mf][1], a[mf][2], a[mf][3], sb + OFF_A + SW(off));
        }
        // W is [n][k] k-contiguous: NON-trans ldmatrix over n-rows yields the
        // exact mma.sync B fragment.
        uint32_t whi[4][2], wlo[4][2];
#pragma unroll
        for (int nn = 0; nn < 2; nn++) {
            int off = (rowB + nn * 16) * 128 + colB + k16 * 32;
            uint32_t r0, r1, r2, r3;
            LDSM_X4(r0, r1, r2, r3, sb + OFF_W_HI + SW(off));
            whi[nn * 2 + 0][0] = r0; whi[nn * 2 + 0][1] = r2;
            whi[nn * 2 + 1][0] = r1; whi[nn * 2 + 1][1] = r3;
            LDSM_X4(r0, r1, r2, r3, sb + OFF_W_LO + SW(off));
            wlo[nn * 2 + 0][0] = r0; wlo[nn * 2 + 0][1] = r2;
            wlo[nn * 2 + 1][0] = r1; wlo[nn * 2 + 1][1] = r3;
        }
#pragma unroll
        for (int mf = 0; mf < 2; mf++)
#pragma unroll
            for (int nf = 0; nf < 4; nf++) {
                MMA_F16(acc[mf][nf], a[mf], whi[nf]);
                MMA_F16(acc[mf][nf], a[mf], wlo[nf]);
            }
    }
}

// ---------------- persistent LSTM kernel ----------------
__global__ void __launch_bounds__(NTH, 1) lstm_mma_kernel(
    const float* __restrict__ Wph, const float* __restrict__ bp, float* __restrict__ out)
{
    extern __shared__ char smem[];
    const uint32_t sbase = smem_to_u32(smem);
    const int tid  = threadIdx.x;
    const int wid  = tid >> 5;
    const int lane = tid & 31;
    const int m0w  = (wid >> 1) * 32;
    const int n0w  = (wid & 1) * 32;
    const int mt   = blockIdx.x >> 6;     // 0..1
    const int nt   = blockIdx.x & 63;     // 0..63
    const int m0   = mt * 128;
    const int n0   = nt * 64;
    const int j0   = nt * 16 + (n0w >> 2);
    const int gid  = lane >> 2;
    const int tid4 = lane & 3;

    // per-thread bias for owned (u2, gate) cells
    float biasr[2][4];
#pragma unroll
    for (int u2 = 0; u2 < 2; u2++)
#pragma unroll
        for (int g = 0; g < 4; g++) {
            int o = (u2 * 2 + (g >> 1)) * 8 + tid4 * 2 + (g & 1);
            biasr[u2][g] = g_bcat[n0 + n0w + o];
        }

    // c-state in registers: [mf][hr][u2]
    float cst[2][2][2];
#pragma unroll
    for (int a = 0; a < 2; a++)
#pragma unroll
        for (int b = 0; b < 2; b++)
#pragma unroll
            for (int cdx = 0; cdx < 2; cdx++) cst[a][b][cdx] = 0.0f;

#define SBUF(s) (sbase + (uint32_t)(s) * STG_STRIDE)

    // prime: slabs 0,1 of t=0 (x region only)
    stage_load(SBUF(0), 0, m0, n0, 0 * KBLK, tid, g_h16[0]); CP_COMMIT();
    stage_load(SBUF(1), 0, m0, n0, 1 * KBLK, tid, g_h16[0]); CP_COMMIT();

    for (int t = 0; t < TT; t++) {
        const int rb = t & 1;
        const int wb = rb ^ 1;
        const __half* hrd = g_h16[rb];

        float acc[2][4][4];
#pragma unroll
        for (int mf = 0; mf < 2; mf++)
#pragma unroll
            for (int nf = 0; nf < 4; nf++)
#pragma unroll
                for (int e = 0; e < 4; e++) acc[mf][nf][e] = 0.0f;

        // first h-dependent slab, right after the barrier released us
        stage_load(SBUF(2), t, m0, n0, 2 * KBLK, tid, hrd); CP_COMMIT();

        // main pipeline: at iter kc, slabs {kc, kc+1, kc+2} in flight
        for (int kc = 0; kc < NKB - 2; kc++) {       // kc = 0..17
            CP_WAIT2();
            __syncthreads();
            compute_stage(SBUF(kc & 3), lane, m0w, n0w, acc);
            if (kc < NKB - 3) {
                stage_load(SBUF((kc + 3) & 3), t, m0, n0, (kc + 3) * KBLK, tid, hrd);
                CP_COMMIT();
            }
        }
        CP_WAIT1(); __syncthreads();
        compute_stage(SBUF(18 & 3), lane, m0w, n0w, acc);
        CP_WAIT0(); __syncthreads();
        compute_stage(SBUF(19 & 3), lane, m0w, n0w, acc);

        // gate math + state update, all in-register
#pragma unroll
        for (int mf = 0; mf < 2; mf++)
#pragma unroll
            for (int hr = 0; hr < 2; hr++) {
                const int m = m0 + m0w + mf * 16 + gid + hr * 8;
#pragma unroll
                for (int u2 = 0; u2 < 2; u2++) {
                    float pg = acc[mf][u2 * 2 + 0][hr * 2 + 0] + biasr[u2][0];
                    float pi = acc[mf][u2 * 2 + 0][hr * 2 + 1] + biasr[u2][1];
                    float pf = acc[mf][u2 * 2 + 1][hr * 2 + 0] + biasr[u2][2];
                    float po = acc[mf][u2 * 2 + 1][hr * 2 + 1] + biasr[u2][3];
                    float gt = tanhfast(pg);
                    float it = sigf(pi);
                    float ft = sigf(pf);
                    float ot = sigf(po);
                    float cn = gt * it + cst[mf][hr][u2] * ft;
                    cst[mf][hr][u2] = cn;
                    float hv = tanhfast(cn) * ot;
                    const int j = j0 + u2 * 4 + tid4;
                    size_t o = (size_t)m * HH + j;
                    g_h16[wb][o] = __float2half_rn(hv);
                    if (t == TT - 1) g_hf[o] = hv;
                }
            }

        // all warps done with stage buffers before overwriting buf0/buf1
        __syncthreads();

        // prefetch t+1 slabs 0,1 (x region, no h dependency) BEFORE the barrier
        if (t + 1 < TT) {
            stage_load(SBUF(0), t + 1, m0, n0, 0 * KBLK, tid, hrd); CP_COMMIT();
            stage_load(SBUF(1), t + 1, m0, n0, 1 * KBLK, tid, hrd); CP_COMMIT();
        }

        grid_sync((unsigned)(t + 1) * GRID);
    }

    // final projection: out[b][cc] = g_hf[b] . Wph[:,cc] + bp[cc]
    {
        const int gidx = blockIdx.x * NTH + tid;   // 0..32767 = 256 x 128
        const int b  = gidx >> 7;
        const int cc = gidx & 127;
        const float* hrow = g_hf + (size_t)b * HH;
        float s = 0.0f;
#pragma unroll 8
        for (int k = 0; k < HH; k++) s += hrow[k] * Wph[(size_t)k * CCC + cc];
        out[gidx] = s + bp[cc];
    }
#undef SBUF
}

// ---------------- launch ----------------
extern "C" void kernel_launch(void* const* d_in, const int* in_sizes, int n_in,
                              void* d_out, int out_size)
{
    (void)in_sizes; (void)n_in; (void)out_size;
    const float* x   = (const float*)d_in[0];
    const float* Wgx = (const float*)d_in[1];
    const float* Wgh = (const float*)d_in[2];
    const float* bg  = (const float*)d_in[3];
    const float* Wix = (const float*)d_in[4];
    const float* Wih = (const float*)d_in[5];
    const float* bi  = (const float*)d_in[6];
    const float* Wfx = (const float*)d_in[7];
    const float* Wfh = (const float*)d_in[8];
    const float* bf  = (const float*)d_in[9];
    const float* Wox = (const float*)d_in[10];
    const float* Woh = (const float*)d_in[11];
    const float* bo  = (const float*)d_in[12];
    const float* Wph = (const float*)d_in[13];
    const float* bp  = (const float*)d_in[14];

    cudaFuncSetAttribute(lstm_mma_kernel, cudaFuncAttributeMaxDynamicSharedMemorySize, SMEM_TOTAL);

    pack_w_kernel<<<512, 256>>>(Wgx, Wgh, Wix, Wih, Wfx, Wfh, Wox, Woh, bg, bi, bf, bo);
    pack_x_kernel<<<2048, 256>>>(x);
    lstm_mma_kernel<<<GRID, NTH, SMEM_TOTAL>>>(Wph, bp, (float*)d_out);
}

// round 13
// speedup vs baseline: 4.7289x; 1.5078x over previous
#include <cuda_runtime.h>
#include <cuda_fp16.h>
#include <math.h>
#include <stdint.h>

// LSTM B=256,T=512,D=256,H=1024,C=128.
// Persistent kernel on mma.sync fp16 (single fp16 W term, fp16 A), fp32 accum.
// 128 CTAs = 2 Mtiles(128) x 64 Ntiles(64); grid barrier per timestep.
// 4-stage cp.async pipeline, h double-buffered across steps.

#define BB   256
#define TT   512
#define DD   256
#define HH   1024
#define CCC  128
#define KTOT 1280
#define NTOT 4096
#define GRID 128
#define NTH  256
#define KBLK 64
#define NKB  (KTOT / KBLK)   // 20

// dynamic smem: FOUR stages of {A 16K, W 8K}
#define STG_STRIDE 24576
#define OFF_A      0
#define OFF_W      16384
#define NSTG       4
#define SMEM_TOTAL (NSTG * STG_STRIDE)   // 98304

#define SW(o) ((o) ^ (((o) >> 3) & 0x70))

// ---------------- device globals ----------------
__device__ __half g_W16[(size_t)NTOT * KTOT];
__device__ float  g_bcat[NTOT];
__device__ __half g_x16[(size_t)TT * BB * DD];
__device__ __half g_h16[2][BB * HH];   // double-buffered across steps
__device__ float  g_hf[BB * HH];
__device__ unsigned g_bar;

// ---------------- PTX helpers ----------------
__device__ __forceinline__ uint32_t smem_to_u32(const void* p) {
    uint32_t a;
    asm("{ .reg .u64 t; cvta.to.shared.u64 t, %1; cvt.u32.u64 %0, t; }" : "=r"(a) : "l"(p));
    return a;
}

#define CP16(dst, src) \
    asm volatile("cp.async.cg.shared.global [%0], [%1], 16;" :: "r"(dst), "l"(src) : "memory")
#define CP_COMMIT() asm volatile("cp.async.commit_group;" ::: "memory")
#define CP_WAIT0()  asm volatile("cp.async.wait_group 0;" ::: "memory")
#define CP_WAIT1()  asm volatile("cp.async.wait_group 1;" ::: "memory")
#define CP_WAIT2()  asm volatile("cp.async.wait_group 2;" ::: "memory")

#define LDSM_X4(r0, r1, r2, r3, addr) \
    asm volatile("ldmatrix.sync.aligned.m8n8.x4.shared.b16 {%0,%1,%2,%3}, [%4];" \
                 : "=r"(r0), "=r"(r1), "=r"(r2), "=r"(r3) : "r"(addr))

#define MMA_F16(c, a, b) \
    asm volatile("mma.sync.aligned.m16n8k16.row.col.f32.f16.f16.f32 " \
                 "{%0,%1,%2,%3},{%4,%5,%6,%7},{%8,%9},{%0,%1,%2,%3};" \
                 : "+f"((c)[0]), "+f"((c)[1]), "+f"((c)[2]), "+f"((c)[3]) \
                 : "r"((a)[0]), "r"((a)[1]), "r"((a)[2]), "r"((a)[3]), \
                   "r"((b)[0]), "r"((b)[1]))

// ---------------- column interleave mapping ----------------
// Within each 32-col warp tile: col(u,g) = 16*(u>>2) + 8*(g>>1) + 2*(u&3) + (g&1)
// => u = ((o>>4)<<2) + ((o>>1)&3),  g = ((o>>3)&1)*2 + (o&1)
// Global: n = w32*32 + o,  hidden j = w32*8 + u.

// ---------------- init kernels ----------------
__global__ void pack_w_kernel(
    const float* __restrict__ Wgx, const float* __restrict__ Wgh,
    const float* __restrict__ Wix, const float* __restrict__ Wih,
    const float* __restrict__ Wfx, const float* __restrict__ Wfh,
    const float* __restrict__ Wox, const float* __restrict__ Woh,
    const float* __restrict__ bg,  const float* __restrict__ bi,
    const float* __restrict__ bf,  const float* __restrict__ bo)
{
    const long total = (long)NTOT * KTOT;
    for (long idx = (long)blockIdx.x * blockDim.x + threadIdx.x; idx < total;
         idx += (long)gridDim.x * blockDim.x) {
        int n = (int)(idx / KTOT);
        int k = (int)(idx % KTOT);
        int o = n & 31;
        int w32 = n >> 5;
        int u = ((o >> 4) << 2) + ((o >> 1) & 3);
        int g = ((o >> 3) & 1) * 2 + (o & 1);
        int j = w32 * 8 + u;
        float w;
        if (k < DD) {
            const float* src = (g == 0) ? Wgx : (g == 1) ? Wix : (g == 2) ? Wfx : Wox;
            w = src[(size_t)k * HH + j];
        } else {
            const float* src = (g == 0) ? Wgh : (g == 1) ? Wih : (g == 2) ? Wfh : Woh;
            w = src[(size_t)(k - DD) * HH + j];
        }
        g_W16[idx] = __float2half_rn(w);

        if (idx < NTOT) {
            int nb  = (int)idx;
            int ob  = nb & 31;
            int wb  = nb >> 5;
            int ub  = ((ob >> 4) << 2) + ((ob >> 1) & 3);
            int gb  = ((ob >> 3) & 1) * 2 + (ob & 1);
            int jb  = wb * 8 + ub;
            const float* bsrc = (gb == 0) ? bg : (gb == 1) ? bi : (gb == 2) ? bf : bo;
            g_bcat[nb] = bsrc[jb];
        }
        if (idx < (long)BB * HH) {
            g_h16[0][idx] = __float2half_rn(0.0f);
            g_h16[1][idx] = __float2half_rn(0.0f);
        }
        if (idx == 0) g_bar = 0u;
    }
}

__global__ void pack_x_kernel(const float* __restrict__ x)
{
    const long total = (long)TT * BB * DD;
    for (long idx = (long)blockIdx.x * blockDim.x + threadIdx.x; idx < total;
         idx += (long)gridDim.x * blockDim.x) {
        int t = (int)(idx / (BB * DD));
        int r = (int)(idx % (BB * DD));
        int b = r / DD;
        int d = r % DD;
        g_x16[idx] = __float2half_rn(x[((size_t)b * TT + t) * DD + d]);
    }
}

// ---------------- grid barrier ----------------
__device__ __forceinline__ void grid_sync(unsigned target)
{
    __syncthreads();
    if (threadIdx.x == 0) {
        asm volatile("red.release.gpu.global.add.u32 [%0], %1;" :: "l"(&g_bar), "r"(1u) : "memory");
        unsigned v;
        do {
            asm volatile("ld.acquire.gpu.global.u32 %0, [%1];" : "=r"(v) : "l"(&g_bar) : "memory");
        } while (v < target);
    }
    __syncthreads();
}

__device__ __forceinline__ float sigf(float x) { return 1.0f / (1.0f + __expf(-x)); }
__device__ __forceinline__ float tanhfast(float x) { return 2.0f * sigf(2.0f * x) - 1.0f; }

// ---------------- staging: gmem -> smem via cp.async ----------------
__device__ __forceinline__ void stage_load(uint32_t sb, int t, int m0, int n0,
                                           int k0, int tid,
                                           const __half* __restrict__ hrd)
{
#pragma unroll
    for (int i = 0; i < 4; i++) {
        int idx = tid + i * NTH;       // 0..1023
        int row = idx >> 3;            // 0..127
        int q   = idx & 7;
        const __half* ph;
        if (k0 < DD) {
            ph = g_x16 + ((size_t)t * BB + (m0 + row)) * DD + k0 + q * 8;
        } else {
            ph = hrd + (size_t)(m0 + row) * HH + (k0 - DD) + q * 8;
        }
        CP16(sb + OFF_A + SW(row * 128 + q * 16), ph);
    }
#pragma unroll
    for (int i = 0; i < 2; i++) {
        int idx = tid + i * NTH;       // 0..511
        int row = idx >> 3;            // 0..63
        int q   = idx & 7;
        CP16(sb + OFF_W + SW(row * 128 + q * 16),
             g_W16 + (size_t)(n0 + row) * KTOT + k0 + q * 8);
    }
}

// ---------------- per-stage compute: 64-K slab, 1 term ----------------
__device__ __forceinline__ void compute_stage(uint32_t sb, int lane, int m0w, int n0w,
                                              float acc[2][4][4])
{
    const int rowA = m0w + (lane & 15);
    const int colA = (lane >> 4) * 16;
    const int rowB = n0w + (lane & 15);
    const int colB = (lane >> 4) * 16;

#pragma unroll
    for (int k16 = 0; k16 < 4; k16++) {
        uint32_t a[2][4];
#pragma unroll
        for (int mf = 0; mf < 2; mf++) {
            int off = (rowA + mf * 16) * 128 + colA + k16 * 32;
            LDSM_X4(a[mf][0], a[mf][1], a[mf][2], a[mf][3], sb + OFF_A + SW(off));
        }
        // W is [n][k] k-contiguous: NON-trans ldmatrix over n-rows yields the
        // exact mma.sync B fragment.
        uint32_t w[4][2];
#pragma unroll
        for (int nn = 0; nn < 2; nn++) {
            int off = (rowB + nn * 16) * 128 + colB + k16 * 32;
            uint32_t r0, r1, r2, r3;
            LDSM_X4(r0, r1, r2, r3, sb + OFF_W + SW(off));
            w[nn * 2 + 0][0] = r0; w[nn * 2 + 0][1] = r2;
            w[nn * 2 + 1][0] = r1; w[nn * 2 + 1][1] = r3;
        }
#pragma unroll
        for (int mf = 0; mf < 2; mf++)
#pragma unroll
            for (int nf = 0; nf < 4; nf++)
                MMA_F16(acc[mf][nf], a[mf], w[nf]);
    }
}

// ---------------- persistent LSTM kernel ----------------
__global__ void __launch_bounds__(NTH, 1) lstm_mma_kernel(
    const float* __restrict__ Wph, const float* __restrict__ bp, float* __restrict__ out)
{
    extern __shared__ char smem[];
    const uint32_t sbase = smem_to_u32(smem);
    const int tid  = threadIdx.x;
    const int wid  = tid >> 5;
    const int lane = tid & 31;
    const int m0w  = (wid >> 1) * 32;
    const int n0w  = (wid & 1) * 32;
    const int mt   = blockIdx.x >> 6;     // 0..1
    const int nt   = blockIdx.x & 63;     // 0..63
    const int m0   = mt * 128;
    const int n0   = nt * 64;
    const int j0   = nt * 16 + (n0w >> 2);
    const int gid  = lane >> 2;
    const int tid4 = lane & 3;

    // per-thread bias for owned (u2, gate) cells
    float biasr[2][4];
#pragma unroll
    for (int u2 = 0; u2 < 2; u2++)
#pragma unroll
        for (int g = 0; g < 4; g++) {
            int o = (u2 * 2 + (g >> 1)) * 8 + tid4 * 2 + (g & 1);
            biasr[u2][g] = g_bcat[n0 + n0w + o];
        }

    // c-state in registers: [mf][hr][u2]
    float cst[2][2][2];
#pragma unroll
    for (int a = 0; a < 2; a++)
#pragma unroll
        for (int b = 0; b < 2; b++)
#pragma unroll
            for (int cdx = 0; cdx < 2; cdx++) cst[a][b][cdx] = 0.0f;

#define SBUF(s) (sbase + (uint32_t)(s) * STG_STRIDE)

    // prime: slabs 0,1 of t=0 (x region only)
    stage_load(SBUF(0), 0, m0, n0, 0 * KBLK, tid, g_h16[0]); CP_COMMIT();
    stage_load(SBUF(1), 0, m0, n0, 1 * KBLK, tid, g_h16[0]); CP_COMMIT();

    for (int t = 0; t < TT; t++) {
        const int rb = t & 1;
        const int wb = rb ^ 1;
        const __half* hrd = g_h16[rb];

        float acc[2][4][4];
#pragma unroll
        for (int mf = 0; mf < 2; mf++)
#pragma unroll
            for (int nf = 0; nf < 4; nf++)
#pragma unroll
                for (int e = 0; e < 4; e++) acc[mf][nf][e] = 0.0f;

        // first h-dependent slab, right after the barrier released us
        stage_load(SBUF(2), t, m0, n0, 2 * KBLK, tid, hrd); CP_COMMIT();

        // main pipeline: at iter kc, slabs {kc, kc+1, kc+2} in flight
        for (int kc = 0; kc < NKB - 2; kc++) {       // kc = 0..17
            CP_WAIT2();
            __syncthreads();
            compute_stage(SBUF(kc & 3), lane, m0w, n0w, acc);
            if (kc < NKB - 3) {
                stage_load(SBUF((kc + 3) & 3), t, m0, n0, (kc + 3) * KBLK, tid, hrd);
                CP_COMMIT();
            }
        }
        CP_WAIT1(); __syncthreads();
        compute_stage(SBUF(18 & 3), lane, m0w, n0w, acc);
        CP_WAIT0(); __syncthreads();
        compute_stage(SBUF(19 & 3), lane, m0w, n0w, acc);

        // gate math + state update, all in-register
#pragma unroll
        for (int mf = 0; mf < 2; mf++)
#pragma unroll
            for (int hr = 0; hr < 2; hr++) {
                const int m = m0 + m0w + mf * 16 + gid + hr * 8;
#pragma unroll
                for (int u2 = 0; u2 < 2; u2++) {
                    float pg = acc[mf][u2 * 2 + 0][hr * 2 + 0] + biasr[u2][0];
                    float pi = acc[mf][u2 * 2 + 0][hr * 2 + 1] + biasr[u2][1];
                    float pf = acc[mf][u2 * 2 + 1][hr * 2 + 0] + biasr[u2][2];
                    float po = acc[mf][u2 * 2 + 1][hr * 2 + 1] + biasr[u2][3];
                    float gt = tanhfast(pg);
                    float it = sigf(pi);
                    float ft = sigf(pf);
                    float ot = sigf(po);
                    float cn = gt * it + cst[mf][hr][u2] * ft;
                    cst[mf][hr][u2] = cn;
                    float hv = tanhfast(cn) * ot;
                    const int j = j0 + u2 * 4 + tid4;
                    size_t o = (size_t)m * HH + j;
                    g_h16[wb][o] = __float2half_rn(hv);
                    if (t == TT - 1) g_hf[o] = hv;
                }
            }

        // all warps done with stage buffers before overwriting buf0/buf1
        __syncthreads();

        // prefetch t+1 slabs 0,1 (x region, no h dependency) BEFORE the barrier
        if (t + 1 < TT) {
            stage_load(SBUF(0), t + 1, m0, n0, 0 * KBLK, tid, hrd); CP_COMMIT();
            stage_load(SBUF(1), t + 1, m0, n0, 1 * KBLK, tid, hrd); CP_COMMIT();
        }

        grid_sync((unsigned)(t + 1) * GRID);
    }

    // final projection: out[b][cc] = g_hf[b] . Wph[:,cc] + bp[cc]
    {
        const int gidx = blockIdx.x * NTH + tid;   // 0..32767 = 256 x 128
        const int b  = gidx >> 7;
        const int cc = gidx & 127;
        const float* hrow = g_hf + (size_t)b * HH;
        float s = 0.0f;
#pragma unroll 8
        for (int k = 0; k < HH; k++) s += hrow[k] * Wph[(size_t)k * CCC + cc];
        out[gidx] = s + bp[cc];
    }
#undef SBUF
}

// ---------------- launch ----------------
extern "C" void kernel_launch(void* const* d_in, const int* in_sizes, int n_in,
                              void* d_out, int out_size)
{
    (void)in_sizes; (void)n_in; (void)out_size;
    const float* x   = (const float*)d_in[0];
    const float* Wgx = (const float*)d_in[1];
    const float* Wgh = (const float*)d_in[2];
    const float* bg  = (const float*)d_in[3];
    const float* Wix = (const float*)d_in[4];
    const float* Wih = (const float*)d_in[5];
    const float* bi  = (const float*)d_in[6];
    const float* Wfx = (const float*)d_in[7];
    const float* Wfh = (const float*)d_in[8];
    const float* bf  = (const float*)d_in[9];
    const float* Wox = (const float*)d_in[10];
    const float* Woh = (const float*)d_in[11];
    const float* bo  = (const float*)d_in[12];
    const float* Wph = (const float*)d_in[13];
    const float* bp  = (const float*)d_in[14];

    cudaFuncSetAttribute(lstm_mma_kernel, cudaFuncAttributeMaxDynamicSharedMemorySize, SMEM_TOTAL);

    pack_w_kernel<<<512, 256>>>(Wgx, Wgh, Wix, Wih, Wfx, Wfh, Wox, Woh, bg, bi, bf, bo);
    pack_x_kernel<<<2048, 256>>>(x);
    lstm_mma_kernel<<<GRID, NTH, SMEM_TOTAL>>>(Wph, bp, (float*)d_out);
}

// round 15
// speedup vs baseline: 5.1587x; 1.0909x over previous
#include <cuda_runtime.h>
#include <cuda_fp16.h>
#include <math.h>
#include <stdint.h>

// LSTM B=256,T=512,D=256,H=1024,C=128.
// Persistent kernel on mma.sync fp16 (single fp16 W, fp16 A), fp32 accum.
// 128 CTAs = 2 Mtiles(128) x 64 Ntiles(64).
// R10: W resident in smem (160KB), A-only 4-stage cp.async pipeline,
// split grid barrier with the 4 x-slabs of t+1 computed between arrive and
// wait, and (fix vs R9) a FINAL barrier before the output projection.

#define BB   256
#define TT   512
#define DD   256
#define HH   1024
#define CCC  128
#define KTOT 1280
#define NTOT 4096
#define GRID 128
#define NTH  256
#define KBLK 64
#define NKB  (KTOT / KBLK)   // 20

// dynamic smem: W resident (20 slabs x 8KB) + FOUR A stages (16KB each)
#define OFF_W      0
#define OFF_AST    163840
#define STG_STRIDE 16384
#define SMEM_TOTAL 229376    // 163840 + 4*16384

#define SW(o) ((o) ^ (((o) >> 3) & 0x70))

// ---------------- device globals ----------------
__device__ __half g_W16[(size_t)NTOT * KTOT];
__device__ float  g_bcat[NTOT];
__device__ __half g_x16[(size_t)TT * BB * DD];
__device__ __half g_h16[2][BB * HH];   // double-buffered across steps
__device__ float  g_hf[BB * HH];
__device__ unsigned g_bar;

// ---------------- PTX helpers ----------------
__device__ __forceinline__ uint32_t smem_to_u32(const void* p) {
    uint32_t a;
    asm("{ .reg .u64 t; cvta.to.shared.u64 t, %1; cvt.u32.u64 %0, t; }" : "=r"(a) : "l"(p));
    return a;
}

#define CP16(dst, src) \
    asm volatile("cp.async.cg.shared.global [%0], [%1], 16;" :: "r"(dst), "l"(src) : "memory")
#define CP_COMMIT() asm volatile("cp.async.commit_group;" ::: "memory")
#define CP_WAIT0()  asm volatile("cp.async.wait_group 0;" ::: "memory")
#define CP_WAIT1()  asm volatile("cp.async.wait_group 1;" ::: "memory")
#define CP_WAIT2()  asm volatile("cp.async.wait_group 2;" ::: "memory")
#define CP_WAIT3()  asm volatile("cp.async.wait_group 3;" ::: "memory")

#define LDSM_X4(r0, r1, r2, r3, addr) \
    asm volatile("ldmatrix.sync.aligned.m8n8.x4.shared.b16 {%0,%1,%2,%3}, [%4];" \
                 : "=r"(r0), "=r"(r1), "=r"(r2), "=r"(r3) : "r"(addr))

#define MMA_F16(c, a, b) \
    asm volatile("mma.sync.aligned.m16n8k16.row.col.f32.f16.f16.f32 " \
                 "{%0,%1,%2,%3},{%4,%5,%6,%7},{%8,%9},{%0,%1,%2,%3};" \
                 : "+f"((c)[0]), "+f"((c)[1]), "+f"((c)[2]), "+f"((c)[3]) \
                 : "r"((a)[0]), "r"((a)[1]), "r"((a)[2]), "r"((a)[3]), \
                   "r"((b)[0]), "r"((b)[1]))

// ---------------- column interleave mapping ----------------
// Within each 32-col warp tile: col(u,g) = 16*(u>>2) + 8*(g>>1) + 2*(u&3) + (g&1)
// => u = ((o>>4)<<2) + ((o>>1)&3),  g = ((o>>3)&1)*2 + (o&1)
// Global: n = w32*32 + o,  hidden j = w32*8 + u.

// ---------------- init kernels ----------------
__global__ void pack_w_kernel(
    const float* __restrict__ Wgx, const float* __restrict__ Wgh,
    const float* __restrict__ Wix, const float* __restrict__ Wih,
    const float* __restrict__ Wfx, const float* __restrict__ Wfh,
    const float* __restrict__ Wox, const float* __restrict__ Woh,
    const float* __restrict__ bg,  const float* __restrict__ bi,
    const float* __restrict__ bf,  const float* __restrict__ bo)
{
    const long total = (long)NTOT * KTOT;
    for (long idx = (long)blockIdx.x * blockDim.x + threadIdx.x; idx < total;
         idx += (long)gridDim.x * blockDim.x) {
        int n = (int)(idx / KTOT);
        int k = (int)(idx % KTOT);
        int o = n & 31;
        int w32 = n >> 5;
        int u = ((o >> 4) << 2) + ((o >> 1) & 3);
        int g = ((o >> 3) & 1) * 2 + (o & 1);
        int j = w32 * 8 + u;
        float w;
        if (k < DD) {
            const float* src = (g == 0) ? Wgx : (g == 1) ? Wix : (g == 2) ? Wfx : Wox;
            w = src[(size_t)k * HH + j];
        } else {
            const float* src = (g == 0) ? Wgh : (g == 1) ? Wih : (g == 2) ? Wfh : Woh;
            w = src[(size_t)(k - DD) * HH + j];
        }
        g_W16[idx] = __float2half_rn(w);

        if (idx < NTOT) {
            int nb  = (int)idx;
            int ob  = nb & 31;
            int wb  = nb >> 5;
            int ub  = ((ob >> 4) << 2) + ((ob >> 1) & 3);
            int gb  = ((ob >> 3) & 1) * 2 + (ob & 1);
            int jb  = wb * 8 + ub;
            const float* bsrc = (gb == 0) ? bg : (gb == 1) ? bi : (gb == 2) ? bf : bo;
            g_bcat[nb] = bsrc[jb];
        }
        if (idx < (long)BB * HH) {
            g_h16[0][idx] = __float2half_rn(0.0f);
            g_h16[1][idx] = __float2half_rn(0.0f);
        }
        if (idx == 0) g_bar = 0u;
    }
}

__global__ void pack_x_kernel(const float* __restrict__ x)
{
    const long total = (long)TT * BB * DD;
    for (long idx = (long)blockIdx.x * blockDim.x + threadIdx.x; idx < total;
         idx += (long)gridDim.x * blockDim.x) {
        int t = (int)(idx / (BB * DD));
        int r = (int)(idx % (BB * DD));
        int b = r / DD;
        int d = r % DD;
        g_x16[idx] = __float2half_rn(x[((size_t)b * TT + t) * DD + d]);
    }
}

// ---------------- split grid barrier ----------------
__device__ __forceinline__ void grid_arrive()
{
    // caller must __syncthreads() before this so all CTA writes precede release
    if (threadIdx.x == 0)
        asm volatile("red.release.gpu.global.add.u32 [%0], %1;" :: "l"(&g_bar), "r"(1u) : "memory");
}
__device__ __forceinline__ void grid_wait(unsigned target)
{
    if (threadIdx.x == 0) {
        unsigned v;
        do {
            asm volatile("ld.acquire.gpu.global.u32 %0, [%1];" : "=r"(v) : "l"(&g_bar) : "memory");
        } while (v < target);
    }
    __syncthreads();
}

__device__ __forceinline__ float sigf(float x) { return 1.0f / (1.0f + __expf(-x)); }
__device__ __forceinline__ float tanhfast(float x) { return 2.0f * sigf(2.0f * x) - 1.0f; }

// ---------------- A staging: gmem -> smem via cp.async (A only) ----------------
__device__ __forceinline__ void stage_A(uint32_t sb, int t, int m0, int k0, int tid,
                                        const __half* __restrict__ hrd)
{
#pragma unroll
    for (int i = 0; i < 4; i++) {
        int idx = tid + i * NTH;       // 0..1023
        int row = idx >> 3;            // 0..127
        int q   = idx & 7;
        const __half* ph;
        if (k0 < DD) {
            ph = g_x16 + ((size_t)t * BB + (m0 + row)) * DD + k0 + q * 8;
        } else {
            ph = hrd + (size_t)(m0 + row) * HH + (k0 - DD) + q * 8;
        }
        CP16(sb + SW(row * 128 + q * 16), ph);
    }
}

// ---------------- per-stage compute: 64-K slab vs resident W slab ----------------
__device__ __forceinline__ void compute_stage(uint32_t sbase, uint32_t sa, int slab,
                                              int lane, int m0w, int n0w,
                                              float acc[2][4][4])
{
    const int rowA = m0w + (lane & 15);
    const int colA = (lane >> 4) * 16;
    const int rowB = slab * 64 + n0w + (lane & 15);
    const int colB = (lane >> 4) * 16;

#pragma unroll
    for (int k16 = 0; k16 < 4; k16++) {
        uint32_t a[2][4];
#pragma unroll
        for (int mf = 0; mf < 2; mf++) {
            int off = (rowA + mf * 16) * 128 + colA + k16 * 32;
            LDSM_X4(a[mf][0], a[mf][1], a[mf][2], a[mf][3], sa + SW(off));
        }
        uint32_t w[4][2];
#pragma unroll
        for (int nn = 0; nn < 2; nn++) {
            int off = (rowB + nn * 16) * 128 + colB + k16 * 32;
            uint32_t r0, r1, r2, r3;
            LDSM_X4(r0, r1, r2, r3, sbase + OFF_W + SW(off));
            w[nn * 2 + 0][0] = r0; w[nn * 2 + 0][1] = r2;
            w[nn * 2 + 1][0] = r1; w[nn * 2 + 1][1] = r3;
        }
#pragma unroll
        for (int mf = 0; mf < 2; mf++)
#pragma unroll
            for (int nf = 0; nf < 4; nf++)
                MMA_F16(acc[mf][nf], a[mf], w[nf]);
    }
}

// ---------------- persistent LSTM kernel ----------------
__global__ void __launch_bounds__(NTH, 1) lstm_mma_kernel(
    const float* __restrict__ Wph, const float* __restrict__ bp, float* __restrict__ out)
{
    extern __shared__ char smem[];
    const uint32_t sbase = smem_to_u32(smem);
    const int tid  = threadIdx.x;
    const int wid  = tid >> 5;
    const int lane = tid & 31;
    const int m0w  = (wid >> 1) * 32;
    const int n0w  = (wid & 1) * 32;
    const int mt   = blockIdx.x >> 6;     // 0..1
    const int nt   = blockIdx.x & 63;     // 0..63
    const int m0   = mt * 128;
    const int n0   = nt * 64;
    const int j0   = nt * 16 + (n0w >> 2);
    const int gid  = lane >> 2;
    const int tid4 = lane & 3;

#define SBUF(s) (sbase + OFF_AST + (uint32_t)(s) * STG_STRIDE)

    // ---- load resident W: 20 slabs x (64 rows x 128B), rows r = slab*64 + nl
#pragma unroll
    for (int i = 0; i < 40; i++) {
        int idx  = tid + i * NTH;         // 0..10239
        int r    = idx >> 3;              // 0..1279
        int q    = idx & 7;
        int slab = r >> 6;
        int nl   = r & 63;
        CP16(sbase + OFF_W + SW(r * 128 + q * 16),
             g_W16 + (size_t)(n0 + nl) * KTOT + slab * KBLK + q * 8);
    }
    CP_COMMIT();

    // x slabs 0..3 of t=0 (h not needed: slabs 0-3 are all k0 < DD)
    stage_A(SBUF(0), 0, m0, 0 * KBLK, tid, g_h16[0]); CP_COMMIT();
    stage_A(SBUF(1), 0, m0, 1 * KBLK, tid, g_h16[0]); CP_COMMIT();
    stage_A(SBUF(2), 0, m0, 2 * KBLK, tid, g_h16[0]); CP_COMMIT();
    stage_A(SBUF(3), 0, m0, 3 * KBLK, tid, g_h16[0]); CP_COMMIT();

    // per-thread bias for owned (u2, gate) cells
    float biasr[2][4];
#pragma unroll
    for (int u2 = 0; u2 < 2; u2++)
#pragma unroll
        for (int g = 0; g < 4; g++) {
            int o = (u2 * 2 + (g >> 1)) * 8 + tid4 * 2 + (g & 1);
            biasr[u2][g] = g_bcat[n0 + n0w + o];
        }

    // c-state in registers
    float cst[2][2][2];
#pragma unroll
    for (int a = 0; a < 2; a++)
#pragma unroll
        for (int b = 0; b < 2; b++)
#pragma unroll
            for (int cdx = 0; cdx < 2; cdx++) cst[a][b][cdx] = 0.0f;

    float acc[2][4][4];
#pragma unroll
    for (int mf = 0; mf < 2; mf++)
#pragma unroll
        for (int nf = 0; nf < 4; nf++)
#pragma unroll
            for (int e = 0; e < 4; e++) acc[mf][nf][e] = 0.0f;

    // t=0 head: compute x slabs 0..3 (W group drains with WAIT3)
    CP_WAIT3(); __syncthreads();
    compute_stage(sbase, SBUF(0), 0, lane, m0w, n0w, acc);
    CP_WAIT2(); __syncthreads();
    compute_stage(sbase, SBUF(1), 1, lane, m0w, n0w, acc);
    CP_WAIT1(); __syncthreads();
    compute_stage(sbase, SBUF(2), 2, lane, m0w, n0w, acc);
    CP_WAIT0(); __syncthreads();
    compute_stage(sbase, SBUF(3), 3, lane, m0w, n0w, acc);

    for (int t = 0; t < TT; t++) {
        const int wb = (t & 1) ^ 1;
        const __half* hrd = g_h16[t & 1];

        // h-dependent slabs 4,5,6 (slab k -> SBUF(k&3))
        stage_A(SBUF(0), t, m0, 4 * KBLK, tid, hrd); CP_COMMIT();
        stage_A(SBUF(1), t, m0, 5 * KBLK, tid, hrd); CP_COMMIT();
        stage_A(SBUF(2), t, m0, 6 * KBLK, tid, hrd); CP_COMMIT();

        // slabs 4..16: keep 3 in flight
        for (int kc = 4; kc < NKB - 3; kc++) {       // kc = 4..16
            CP_WAIT2();
            __syncthreads();
            compute_stage(sbase, SBUF(kc & 3), kc, lane, m0w, n0w, acc);
            stage_A(SBUF((kc + 3) & 3), t, m0, (kc + 3) * KBLK, tid, hrd);
            CP_COMMIT();
        }
        CP_WAIT2(); __syncthreads();
        compute_stage(sbase, SBUF(17 & 3), 17, lane, m0w, n0w, acc);
        CP_WAIT1(); __syncthreads();
        compute_stage(sbase, SBUF(18 & 3), 18, lane, m0w, n0w, acc);
        CP_WAIT0(); __syncthreads();
        compute_stage(sbase, SBUF(19 & 3), 19, lane, m0w, n0w, acc);

        // gate math + state update, all in-register
#pragma unroll
        for (int mf = 0; mf < 2; mf++)
#pragma unroll
            for (int hr = 0; hr < 2; hr++) {
                const int m = m0 + m0w + mf * 16 + gid + hr * 8;
#pragma unroll
                for (int u2 = 0; u2 < 2; u2++) {
                    float pg = acc[mf][u2 * 2 + 0][hr * 2 + 0] + biasr[u2][0];
                    float pi = acc[mf][u2 * 2 + 0][hr * 2 + 1] + biasr[u2][1];
                    float pf = acc[mf][u2 * 2 + 1][hr * 2 + 0] + biasr[u2][2];
                    float po = acc[mf][u2 * 2 + 1][hr * 2 + 1] + biasr[u2][3];
                    float gt = tanhfast(pg);
                    float it = sigf(pi);
                    float ft = sigf(pf);
                    float ot = sigf(po);
                    float cn = gt * it + cst[mf][hr][u2] * ft;
                    cst[mf][hr][u2] = cn;
                    float hv = tanhfast(cn) * ot;
                    const int j = j0 + u2 * 4 + tid4;
                    size_t o = (size_t)m * HH + j;
                    g_h16[wb][o] = __float2half_rn(hv);
                    if (t == TT - 1) g_hf[o] = hv;
                }
            }

        // all threads' h writes + stage-buffer reads done
        __syncthreads();

        if (t + 1 < TT) {
            // prefetch the 4 x-slabs of t+1, announce arrival, compute them
            // WHILE other CTAs finish step t, then wait.
            stage_A(SBUF(0), t + 1, m0, 0 * KBLK, tid, hrd); CP_COMMIT();
            stage_A(SBUF(1), t + 1, m0, 1 * KBLK, tid, hrd); CP_COMMIT();
            stage_A(SBUF(2), t + 1, m0, 2 * KBLK, tid, hrd); CP_COMMIT();
            stage_A(SBUF(3), t + 1, m0, 3 * KBLK, tid, hrd); CP_COMMIT();
            grid_arrive();

#pragma unroll
            for (int mf = 0; mf < 2; mf++)
#pragma unroll
                for (int nf = 0; nf < 4; nf++)
#pragma unroll
                    for (int e = 0; e < 4; e++) acc[mf][nf][e] = 0.0f;

            CP_WAIT3(); __syncthreads();
            compute_stage(sbase, SBUF(0), 0, lane, m0w, n0w, acc);
            CP_WAIT2(); __syncthreads();
            compute_stage(sbase, SBUF(1), 1, lane, m0w, n0w, acc);
            CP_WAIT1(); __syncthreads();
            compute_stage(sbase, SBUF(2), 2, lane, m0w, n0w, acc);
            CP_WAIT0(); __syncthreads();
            compute_stage(sbase, SBUF(3), 3, lane, m0w, n0w, acc);

            grid_wait((unsigned)(t + 1) * GRID);
        } else {
            // FINAL barrier: all CTAs' g_hf writes must land before the
            // projection reads the full h rows (this was the R9 bug).
            grid_arrive();
            grid_wait((unsigned)TT * GRID);
        }
    }

    // final projection: out[b][cc] = g_hf[b] . Wph[:,cc] + bp[cc]
    {
        const int gidx = blockIdx.x * NTH + tid;   // 0..32767 = 256 x 128
        const int b  = gidx >> 7;
        const int cc = gidx & 127;
        const float* hrow = g_hf + (size_t)b * HH;
        float s = 0.0f;
#pragma unroll 8
        for (int k = 0; k < HH; k++) s += hrow[k] * Wph[(size_t)k * CCC + cc];
        out[gidx] = s + bp[cc];
    }
#undef SBUF
}

// ---------------- launch ----------------
extern "C" void kernel_launch(void* const* d_in, const int* in_sizes, int n_in,
                              void* d_out, int out_size)
{
    (void)in_sizes; (void)n_in; (void)out_size;
    const float* x   = (const float*)d_in[0];
    const float* Wgx = (const float*)d_in[1];
    const float* Wgh = (const float*)d_in[2];
    const float* bg  = (const float*)d_in[3];
    const float* Wix = (const float*)d_in[4];
    const float* Wih = (const float*)d_in[5];
    const float* bi  = (const float*)d_in[6];
    const float* Wfx = (const float*)d_in[7];
    const float* Wfh = (const float*)d_in[8];
    const float* bf  = (const float*)d_in[9];
    const float* Wox = (const float*)d_in[10];
    const float* Woh = (const float*)d_in[11];
    const float* bo  = (const float*)d_in[12];
    const float* Wph = (const float*)d_in[13];
    const float* bp  = (const float*)d_in[14];

    cudaFuncSetAttribute(lstm_mma_kernel, cudaFuncAttributeMaxDynamicSharedMemorySize, SMEM_TOTAL);

    pack_w_kernel<<<512, 256>>>(Wgx, Wgh, Wix, Wih, Wfx, Wfh, Wox, Woh, bg, bi, bf, bo);
    pack_x_kernel<<<2048, 256>>>(x);
    lstm_mma_kernel<<<GRID, NTH, SMEM_TOTAL>>>(Wph, bp, (float*)d_out);
}